// round 5
// baseline (speedup 1.0000x reference)
#include <cuda_runtime.h>
#include <math.h>

#define T_STEPS 8192
#define M_DIM   1024
#define N_DIM   2048

#define GBLOCKS        128
#define ROWS_PER_BLOCK 16    // N_DIM / GBLOCKS
#define RNN_THREADS    256
#define WARPS_PER_BLK  8

// Scratch for the batched input projection (allocation-free rule: device global).
__device__ float g_pre[(size_t)T_STEPS * N_DIM];

// Per-WARP flags: block j's 8 warp-flags packed in one 32B sector at
// g_wflags[j*32 .. j*32+7]; blocks padded 128B apart so polls spread over
// ~128 L2 lines/slices. Every flag advances by exactly T_STEPS per launch
// (step 0 publishes base+1, steps 1..8191 publish base+t+1), uniformly across
// all warps, so reading any OWN-block flag at launch start gives the epoch
// base; signed compares handle wrap. No resets -> graph-replay safe.
__device__ unsigned g_wflags[GBLOCKS * 32];

// ---------------------------------------------------------------------------
// Inline PTX helpers
// ---------------------------------------------------------------------------
__device__ __forceinline__ void st_rel_gpu(unsigned* p, unsigned v) {
    asm volatile("st.release.gpu.u32 [%0], %1;" :: "l"(p), "r"(v) : "memory");
}
__device__ __forceinline__ unsigned ld_cv_u32(const unsigned* p) {
    unsigned v;
    asm volatile("ld.global.cv.u32 %0, [%1];" : "=r"(v) : "l"(p) : "memory");
    return v;
}
__device__ __forceinline__ void fma2(unsigned long long& d,
                                     unsigned long long a,
                                     unsigned long long b) {
    asm("fma.rn.f32x2 %0, %1, %2, %3;" : "=l"(d) : "l"(a), "l"(b), "l"(d));
}
__device__ __forceinline__ unsigned long long add2(unsigned long long a,
                                                   unsigned long long b) {
    unsigned long long d;
    asm("add.rn.f32x2 %0, %1, %2;" : "=l"(d) : "l"(a), "l"(b));
    return d;
}
__device__ __forceinline__ float hsum2(unsigned long long v) {
    float lo, hi;
    asm("mov.b64 {%0, %1}, %2;" : "=f"(lo), "=f"(hi) : "l"(v));
    return lo + hi;
}

// ---------------------------------------------------------------------------
// Kernel 1: pre = X @ W_ih^T + (b_ih + b_hh)   (unchanged, proven)
// ---------------------------------------------------------------------------
__global__ __launch_bounds__(256) void gemm_pre_kernel(
    const float* __restrict__ X,
    const float* __restrict__ Wih,
    const float* __restrict__ b_ih,
    const float* __restrict__ b_hh)
{
    __shared__ float As[8][128];
    __shared__ float Bs[8][128];

    const int tid = threadIdx.x;
    const int rowBase = blockIdx.x * 128;
    const int colBase = blockIdx.y * 128;
    const int tx = tid & 15;
    const int ty = tid >> 4;

    float acc[8][8];
#pragma unroll
    for (int i = 0; i < 8; i++)
#pragma unroll
        for (int j = 0; j < 8; j++) acc[i][j] = 0.0f;

    const int lr = tid >> 1;
    const int lq = (tid & 1) * 4;

    for (int k0 = 0; k0 < M_DIM; k0 += 8) {
        float4 av = *(const float4*)&X  [(size_t)(rowBase + lr) * M_DIM + k0 + lq];
        float4 bv = *(const float4*)&Wih[(size_t)(colBase + lr) * M_DIM + k0 + lq];

        __syncthreads();
        As[lq + 0][lr] = av.x;
        As[lq + 1][lr] = av.y;
        As[lq + 2][lr] = av.z;
        As[lq + 3][lr] = av.w;
        Bs[lq + 0][lr] = bv.x;
        Bs[lq + 1][lr] = bv.y;
        Bs[lq + 2][lr] = bv.z;
        Bs[lq + 3][lr] = bv.w;
        __syncthreads();

#pragma unroll
        for (int k = 0; k < 8; k++) {
            float4 a0 = ((const float4*)As[k])[ty];
            float4 a1 = ((const float4*)As[k])[ty + 16];
            float4 b0 = ((const float4*)Bs[k])[tx];
            float4 b1 = ((const float4*)Bs[k])[tx + 16];
            float a[8] = {a0.x, a0.y, a0.z, a0.w, a1.x, a1.y, a1.z, a1.w};
            float b[8] = {b0.x, b0.y, b0.z, b0.w, b1.x, b1.y, b1.z, b1.w};
#pragma unroll
            for (int i = 0; i < 8; i++)
#pragma unroll
                for (int j = 0; j < 8; j++)
                    acc[i][j] = fmaf(a[i], b[j], acc[i][j]);
        }
    }

    const int n0 = colBase + tx * 4;
    const int n1 = colBase + 64 + tx * 4;
    float bias[8];
#pragma unroll
    for (int j = 0; j < 4; j++) {
        bias[j]     = b_ih[n0 + j] + b_hh[n0 + j];
        bias[j + 4] = b_ih[n1 + j] + b_hh[n1 + j];
    }

#pragma unroll
    for (int i = 0; i < 8; i++) {
        int m = rowBase + ((i < 4) ? (ty * 4 + i) : (64 + ty * 4 + (i - 4)));
        float4 o0, o1;
        o0.x = acc[i][0] + bias[0];
        o0.y = acc[i][1] + bias[1];
        o0.z = acc[i][2] + bias[2];
        o0.w = acc[i][3] + bias[3];
        o1.x = acc[i][4] + bias[4];
        o1.y = acc[i][5] + bias[5];
        o1.z = acc[i][6] + bias[6];
        o1.w = acc[i][7] + bias[7];
        *(float4*)&g_pre[(size_t)m * N_DIM + n0] = o0;
        *(float4*)&g_pre[(size_t)m * N_DIM + n1] = o1;
    }
}

// ---------------------------------------------------------------------------
// Kernel 2: persistent RNN recurrence.
// Changes vs round 2:
//   - Per-WARP flags: lane0 (sole writer of its 2 h values) stores Y then
//     releases its own warp-flag. No bottom __syncthreads, no cross-warp
//     ordering needed -> the intra-block straggler max is off the chain.
//   - Detect: threads 0..127 poll block tid's 8 warp-flags (8 scalar cv
//     loads, one 32B sector, slices spread by 128B block padding), bitmask
//     laggard re-poll, then ONE __syncthreads gates compute.
//   - Correctness at any skew: Y addresses are write-once per launch, flags
//     are monotone counters; weak cached h loads are safe (L1 flushed per
//     launch; only own-block stores touch own rows' sectors).
// ---------------------------------------------------------------------------
__global__ __launch_bounds__(RNN_THREADS, 1) void rnn_kernel(
    const float* __restrict__ Whh,
    float* __restrict__ Y)
{
    const int tid  = threadIdx.x;
    const int b    = blockIdx.x;
    const int warp = tid >> 5;
    const int lane = tid & 31;
    const int row0 = b * ROWS_PER_BLOCK + 2 * warp;

    // Warp's two W_hh rows in registers, pre-packed as f32x2 pairs.
    unsigned long long wA[32], wB[32];
    {
        const ulonglong2* WA = (const ulonglong2*)(Whh + (size_t)row0 * N_DIM);
        const ulonglong2* WB = (const ulonglong2*)(Whh + (size_t)(row0 + 1) * N_DIM);
#pragma unroll
        for (int i = 0; i < 16; i++) {
            ulonglong2 va = WA[i * 32 + lane];
            ulonglong2 vb = WB[i * 32 + lane];
            wA[2 * i]     = va.x;
            wA[2 * i + 1] = va.y;
            wB[2 * i]     = vb.x;
            wB[2 * i + 1] = vb.y;
        }
    }

    // Epoch base from an OWN-block flag (only this block writes it, and not
    // before the barrier below; all flags are uniform at launch start).
    const unsigned base = ld_cv_u32(&g_wflags[b * 32]);
    __syncthreads();

    // Step 0: h_0 = 0  =>  Y[0] = tanh(pre[0]); publish warp-flag base+1.
    if (lane == 0) {
        const float2 p0 = *(const float2*)(g_pre + row0);
        float2 o;
        o.x = tanhf(p0.x);
        o.y = tanhf(p0.y);
        *(float2*)(Y + row0) = o;
        st_rel_gpu(&g_wflags[b * 32 + warp], base + 1u);
    }

    // Prefetch pre for step 1.
    float2 pv = *(const float2*)(g_pre + (size_t)N_DIM + row0);

    for (int t = 1; t < T_STEPS; t++) {
        const unsigned target = base + (unsigned)t;

        // Detect: thread tid polls the 8 warp-flags of block tid.
        if (tid < GBLOCKS) {
            const unsigned* f = &g_wflags[tid * 32];
            unsigned done = 0;
            while (done != 0xFFu) {
#pragma unroll
                for (int k = 0; k < WARPS_PER_BLK; k++) {
                    if (!((done >> k) & 1u)) {
                        unsigned v = ld_cv_u32(f + k);
                        if ((int)(v - target) >= 0) done |= (1u << k);
                    }
                }
            }
        }
        __syncthreads();

        // Dot products: rows row0, row0+1 against h_{t-1} = Y[t-1].
        const ulonglong2* Yp = (const ulonglong2*)(Y + (size_t)(t - 1) * N_DIM);
        unsigned long long acc00 = 0ull, acc01 = 0ull, acc10 = 0ull, acc11 = 0ull;
#pragma unroll
        for (int i = 0; i < 16; i++) {
            ulonglong2 hv = Yp[i * 32 + lane];
            fma2(acc00, wA[2 * i],     hv.x);
            fma2(acc01, wA[2 * i + 1], hv.y);
            fma2(acc10, wB[2 * i],     hv.x);
            fma2(acc11, wB[2 * i + 1], hv.y);
        }
        float r0 = hsum2(add2(acc00, acc01));
        float r1 = hsum2(add2(acc10, acc11));

#pragma unroll
        for (int o = 16; o; o >>= 1) {
            r0 += __shfl_xor_sync(0xffffffffu, r0, o);
            r1 += __shfl_xor_sync(0xffffffffu, r1, o);
        }

        // Prefetch next step's pre while the result is written.
        float2 pnext = pv;
        if (t + 1 < T_STEPS)
            pnext = *(const float2*)(g_pre + (size_t)(t + 1) * N_DIM + row0);

        // Publish immediately per-warp: lane0 wrote both rows itself, so its
        // release-store orders exactly the data consumers will read.
        if (lane == 0) {
            float2 o;
            o.x = tanhf(pv.x + r0);
            o.y = tanhf(pv.y + r1);
            *(float2*)(Y + (size_t)t * N_DIM + row0) = o;
            st_rel_gpu(&g_wflags[b * 32 + warp], target + 1u);
        }
        pv = pnext;
    }
}

// ---------------------------------------------------------------------------
extern "C" void kernel_launch(void* const* d_in, const int* in_sizes, int n_in,
                              void* d_out, int out_size)
{
    const float* X   = (const float*)d_in[0];   // [T, M]
    const float* Wih = (const float*)d_in[1];   // [N, M]
    const float* Whh = (const float*)d_in[2];   // [N, N]
    const float* bih = (const float*)d_in[3];   // [N]
    const float* bhh = (const float*)d_in[4];   // [N]
    float* Y = (float*)d_out;                   // [T, N]

    dim3 ggrid(T_STEPS / 128, N_DIM / 128);
    gemm_pre_kernel<<<ggrid, 256>>>(X, Wih, bih, bhh);

    rnn_kernel<<<GBLOCKS, RNN_THREADS>>>(Whh, Y);
}

// round 8
// speedup vs baseline: 1.2275x; 1.2275x over previous
#include <cuda_runtime.h>
#include <math.h>

#define T_STEPS 8192
#define M_DIM   1024
#define N_DIM   2048

#define GBLOCKS        128
#define ROWS_PER_BLOCK 16    // N_DIM / GBLOCKS
#define RNN_THREADS    256

// Scratch for the batched input projection (allocation-free rule: device global).
__device__ float g_pre[(size_t)T_STEPS * N_DIM];

// Distributed barrier flags, one 32B-padded slot per block (R2-proven).
// Flags advance by exactly T_STEPS per launch, uniformly across blocks, so
// reading your OWN slot at launch start gives the epoch base; signed-distance
// compares make polling wraparound-safe. No resets -> graph-replay safe.
__device__ unsigned g_flags[GBLOCKS * 8];   // slot b at g_flags[b*8]

// ---------------------------------------------------------------------------
// Inline PTX helpers
// ---------------------------------------------------------------------------
__device__ __forceinline__ unsigned ld_acq(const unsigned* p) {
    unsigned v;
    asm volatile("ld.acquire.gpu.u32 %0, [%1];" : "=r"(v) : "l"(p) : "memory");
    return v;
}
__device__ __forceinline__ void st_rel(unsigned* p, unsigned v) {
    asm volatile("st.release.gpu.u32 [%0], %1;" :: "l"(p), "r"(v) : "memory");
}
__device__ __forceinline__ void fma2(unsigned long long& d,
                                     unsigned long long a,
                                     unsigned long long b) {
    asm("fma.rn.f32x2 %0, %1, %2, %3;" : "=l"(d) : "l"(a), "l"(b), "l"(d));
}
__device__ __forceinline__ unsigned long long add2(unsigned long long a,
                                                   unsigned long long b) {
    unsigned long long d;
    asm("add.rn.f32x2 %0, %1, %2;" : "=l"(d) : "l"(a), "l"(b));
    return d;
}
__device__ __forceinline__ float hsum2(unsigned long long v) {
    float lo, hi;
    asm("mov.b64 {%0, %1}, %2;" : "=f"(lo), "=f"(hi) : "l"(v));
    return lo + hi;
}

// ---------------------------------------------------------------------------
// Kernel 1: pre = X @ W_ih^T + (b_ih + b_hh)   (unchanged, proven)
// ---------------------------------------------------------------------------
__global__ __launch_bounds__(256) void gemm_pre_kernel(
    const float* __restrict__ X,
    const float* __restrict__ Wih,
    const float* __restrict__ b_ih,
    const float* __restrict__ b_hh)
{
    __shared__ float As[8][128];
    __shared__ float Bs[8][128];

    const int tid = threadIdx.x;
    const int rowBase = blockIdx.x * 128;
    const int colBase = blockIdx.y * 128;
    const int tx = tid & 15;
    const int ty = tid >> 4;

    float acc[8][8];
#pragma unroll
    for (int i = 0; i < 8; i++)
#pragma unroll
        for (int j = 0; j < 8; j++) acc[i][j] = 0.0f;

    const int lr = tid >> 1;
    const int lq = (tid & 1) * 4;

    for (int k0 = 0; k0 < M_DIM; k0 += 8) {
        float4 av = *(const float4*)&X  [(size_t)(rowBase + lr) * M_DIM + k0 + lq];
        float4 bv = *(const float4*)&Wih[(size_t)(colBase + lr) * M_DIM + k0 + lq];

        __syncthreads();
        As[lq + 0][lr] = av.x;
        As[lq + 1][lr] = av.y;
        As[lq + 2][lr] = av.z;
        As[lq + 3][lr] = av.w;
        Bs[lq + 0][lr] = bv.x;
        Bs[lq + 1][lr] = bv.y;
        Bs[lq + 2][lr] = bv.z;
        Bs[lq + 3][lr] = bv.w;
        __syncthreads();

#pragma unroll
        for (int k = 0; k < 8; k++) {
            float4 a0 = ((const float4*)As[k])[ty];
            float4 a1 = ((const float4*)As[k])[ty + 16];
            float4 b0 = ((const float4*)Bs[k])[tx];
            float4 b1 = ((const float4*)Bs[k])[tx + 16];
            float a[8] = {a0.x, a0.y, a0.z, a0.w, a1.x, a1.y, a1.z, a1.w};
            float b[8] = {b0.x, b0.y, b0.z, b0.w, b1.x, b1.y, b1.z, b1.w};
#pragma unroll
            for (int i = 0; i < 8; i++)
#pragma unroll
                for (int j = 0; j < 8; j++)
                    acc[i][j] = fmaf(a[i], b[j], acc[i][j]);
        }
    }

    const int n0 = colBase + tx * 4;
    const int n1 = colBase + 64 + tx * 4;
    float bias[8];
#pragma unroll
    for (int j = 0; j < 4; j++) {
        bias[j]     = b_ih[n0 + j] + b_hh[n0 + j];
        bias[j + 4] = b_ih[n1 + j] + b_hh[n1 + j];
    }

#pragma unroll
    for (int i = 0; i < 8; i++) {
        int m = rowBase + ((i < 4) ? (ty * 4 + i) : (64 + ty * 4 + (i - 4)));
        float4 o0, o1;
        o0.x = acc[i][0] + bias[0];
        o0.y = acc[i][1] + bias[1];
        o0.z = acc[i][2] + bias[2];
        o0.w = acc[i][3] + bias[3];
        o1.x = acc[i][4] + bias[4];
        o1.y = acc[i][5] + bias[5];
        o1.z = acc[i][6] + bias[6];
        o1.w = acc[i][7] + bias[7];
        *(float4*)&g_pre[(size_t)m * N_DIM + n0] = o0;
        *(float4*)&g_pre[(size_t)m * N_DIM + n1] = o1;
    }
}

// ---------------------------------------------------------------------------
// Kernel 2: persistent RNN recurrence.
//   Sync:     R2's proven flag barrier (acquire polls, release publish).
//   W_hh:     register-resident per warp (R2-proven layout) -> no LDS for W.
//   h:        staged into SMEM ONCE per block per step by a cooperative
//             8KB load (R1-proven staging), consumed via conflict-free
//             16B LDS by all 8 warps.
// Per-step per-block traffic: 8KB L2 + 64KB LDS (overlaps FMA issue),
// vs R2's 64KB L2 re-reads / R1's 128KB LDS for W.
// ---------------------------------------------------------------------------
__global__ __launch_bounds__(RNN_THREADS, 1) void rnn_kernel(
    const float* __restrict__ Whh,
    float* __restrict__ Y)
{
    __shared__ float sh[N_DIM];   // 8 KB h staging

    const int tid  = threadIdx.x;
    const int b    = blockIdx.x;
    const int warp = tid >> 5;
    const int lane = tid & 31;
    const int row0 = b * ROWS_PER_BLOCK + 2 * warp;

    // Warp's two W_hh rows in registers, pre-packed as f32x2 pairs.
    unsigned long long wA[32], wB[32];
    {
        const ulonglong2* WA = (const ulonglong2*)(Whh + (size_t)row0 * N_DIM);
        const ulonglong2* WB = (const ulonglong2*)(Whh + (size_t)(row0 + 1) * N_DIM);
#pragma unroll
        for (int i = 0; i < 16; i++) {
            ulonglong2 va = WA[i * 32 + lane];
            ulonglong2 vb = WB[i * 32 + lane];
            wA[2 * i]     = va.x;
            wA[2 * i + 1] = va.y;
            wB[2 * i]     = vb.x;
            wB[2 * i + 1] = vb.y;
        }
    }

    // Epoch base from my own flag slot (uniform across blocks at launch start).
    const unsigned base = g_flags[b * 8];

    // Step 0: h_0 = 0  =>  Y[0] = tanh(pre[0]).
    if (lane == 0) {
        const float2 p0 = *(const float2*)(g_pre + row0);
        float2 o;
        o.x = tanhf(p0.x);
        o.y = tanhf(p0.y);
        *(float2*)(Y + row0) = o;
    }
    __syncthreads();
    if (tid == 0) st_rel(&g_flags[b * 8], base + 1u);

    // Prefetch pre for step 1.
    float2 pv = *(const float2*)(g_pre + (size_t)N_DIM + row0);

    float4* sh4 = (float4*)sh;
    const ulonglong2* hp = (const ulonglong2*)sh;

    for (int t = 1; t < T_STEPS; t++) {
        // Wait until every block has published h_{t-1} (flag >= base + t).
        const unsigned target = base + (unsigned)t;
        if (tid < GBLOCKS) {
            while ((int)(ld_acq(&g_flags[tid * 8]) - target) < 0) { }
        }
        __syncthreads();

        // Stage h_{t-1} = Y[t-1] into SMEM once (8 KB cooperative load).
        const float4* Yp = (const float4*)(Y + (size_t)(t - 1) * N_DIM);
        sh4[tid]       = Yp[tid];
        sh4[tid + 256] = Yp[tid + 256];
        __syncthreads();

        // Dot products from SMEM (conflict-free 16B pattern), W from regs.
        unsigned long long acc00 = 0ull, acc01 = 0ull, acc10 = 0ull, acc11 = 0ull;
#pragma unroll
        for (int i = 0; i < 16; i++) {
            ulonglong2 hv = hp[i * 32 + lane];
            fma2(acc00, wA[2 * i],     hv.x);
            fma2(acc01, wA[2 * i + 1], hv.y);
            fma2(acc10, wB[2 * i],     hv.x);
            fma2(acc11, wB[2 * i + 1], hv.y);
        }
        float r0 = hsum2(add2(acc00, acc01));
        float r1 = hsum2(add2(acc10, acc11));

#pragma unroll
        for (int o = 16; o; o >>= 1) {
            r0 += __shfl_xor_sync(0xffffffffu, r0, o);
            r1 += __shfl_xor_sync(0xffffffffu, r1, o);
        }

        // Prefetch next step's pre while the result is written.
        float2 pnext = pv;
        if (t + 1 < T_STEPS)
            pnext = *(const float2*)(g_pre + (size_t)(t + 1) * N_DIM + row0);

        if (lane == 0) {
            float2 o;
            o.x = tanhf(pv.x + r0);
            o.y = tanhf(pv.y + r1);
            *(float2*)(Y + (size_t)t * N_DIM + row0) = o;
        }
        pv = pnext;

        // Publish h_t: block barrier gives happens-before from all warps'
        // stores to tid0's gpu-scope release (R2-proven pattern).
        __syncthreads();
        if (tid == 0) st_rel(&g_flags[b * 8], base + (unsigned)(t + 1));
    }
}

// ---------------------------------------------------------------------------
extern "C" void kernel_launch(void* const* d_in, const int* in_sizes, int n_in,
                              void* d_out, int out_size)
{
    const float* X   = (const float*)d_in[0];   // [T, M]
    const float* Wih = (const float*)d_in[1];   // [N, M]
    const float* Whh = (const float*)d_in[2];   // [N, N]
    const float* bih = (const float*)d_in[3];   // [N]
    const float* bhh = (const float*)d_in[4];   // [N]
    float* Y = (float*)d_out;                   // [T, N]

    dim3 ggrid(T_STEPS / 128, N_DIM / 128);
    gemm_pre_kernel<<<ggrid, 256>>>(X, Wih, bih, bhh);

    rnn_kernel<<<GBLOCKS, RNN_THREADS>>>(Whh, Y);
}

// round 10
// speedup vs baseline: 1.3834x; 1.1270x over previous
#include <cuda_runtime.h>
#include <math.h>

#define T_STEPS 8192
#define M_DIM   1024
#define N_DIM   2048

#define GBLOCKS  128
#define RPB      16      // rows (of h / pre cols) per block
#define NTHREADS 512     // warps 0-7: gemm(pre), warps 8-15: rnn
#define PRE_RING 64      // pre ring depth (steps)
#define XG       4       // X rows staged per group

// Distributed barrier flags, one 32B-padded slot per block (R2-proven).
// Each launch every flag advances by exactly T_STEPS, uniformly, so your own
// slot at launch start is the epoch base; signed compares handle wrap.
__device__ unsigned g_flags[GBLOCKS * 8];

// ---------------------------------------------------------------------------
// Inline PTX helpers
// ---------------------------------------------------------------------------
__device__ __forceinline__ unsigned ld_acq(const unsigned* p) {
    unsigned v;
    asm volatile("ld.acquire.gpu.u32 %0, [%1];" : "=r"(v) : "l"(p) : "memory");
    return v;
}
__device__ __forceinline__ void st_rel(unsigned* p, unsigned v) {
    asm volatile("st.release.gpu.u32 [%0], %1;" :: "l"(p), "r"(v) : "memory");
}
__device__ __forceinline__ int lds_acq_cta(const int* sp) {
    unsigned a = (unsigned)__cvta_generic_to_shared((void*)sp);
    int v;
    asm volatile("ld.acquire.cta.shared.s32 %0, [%1];" : "=r"(v) : "r"(a) : "memory");
    return v;
}
__device__ __forceinline__ void sts_rel_cta(int* sp, int v) {
    unsigned a = (unsigned)__cvta_generic_to_shared(sp);
    asm volatile("st.release.cta.shared.s32 [%0], %1;" :: "r"(a), "r"(v) : "memory");
}
__device__ __forceinline__ void barx(int id) {   // named barrier, 256 threads
    asm volatile("bar.sync %0, 256;" :: "r"(id) : "memory");
}
__device__ __forceinline__ void fma2(unsigned long long& d,
                                     unsigned long long a,
                                     unsigned long long b) {
    asm("fma.rn.f32x2 %0, %1, %2, %3;" : "=l"(d) : "l"(a), "l"(b), "l"(d));
}
__device__ __forceinline__ unsigned long long add2(unsigned long long a,
                                                   unsigned long long b) {
    unsigned long long d;
    asm("add.rn.f32x2 %0, %1, %2;" : "=l"(d) : "l"(a), "l"(b));
    return d;
}
__device__ __forceinline__ float hsum2(unsigned long long v) {
    float lo, hi;
    asm("mov.b64 {%0, %1}, %2;" : "=f"(lo), "=f"(hi) : "l"(v));
    return lo + hi;
}

// ---------------------------------------------------------------------------
// Fused persistent kernel.
//  SMEM: sW   = W_hh slice [16 x 2048]          (128 KB, loaded once)
//        sX   = X staging  [2][XG x 1024]       ( 32 KB, double buffer)
//        sPre = pre ring   [PRE_RING x 16]      (  4 KB)
//  Warps 0-7 (gemm): warp w computes pre cols 16b+2w, +1 for all t, W_ih
//    rows in regs, X from sX, adds bias, writes sPre, releases sGprog[w].
//  Warps 8-15 (rnn): R2's proven loop: acquire-poll 128 flags, bar, dot
//    products (W from SMEM [R1-proven], h direct from Y [R2-proven]),
//    reduce, read pre[t] from ring, tanh, store Y, release own flag.
// ---------------------------------------------------------------------------
__global__ __launch_bounds__(NTHREADS, 1) void rnn_fused_kernel(
    const float* __restrict__ X,
    const float* __restrict__ Wih,
    const float* __restrict__ Whh,
    const float* __restrict__ b_ih,
    const float* __restrict__ b_hh,
    float* __restrict__ Y)
{
    extern __shared__ float smem[];
    float*          sW   = smem;                 // 32768 floats
    float*          sX   = smem + 32768;         //  8192 floats
    volatile float* sPre = smem + 40960;         //  1024 floats
    __shared__ int          sGprog[8];           // gemm rows produced (per warp)
    __shared__ volatile int sCprog[8];           // rnn rows consumed (per warp)

    const int tid  = threadIdx.x;
    const int b    = blockIdx.x;
    const int warp = tid >> 5;
    const int lane = tid & 31;

    // Load this block's W_hh slice into SMEM once (all 512 threads).
    {
        const float4* src = (const float4*)(Whh + (size_t)b * RPB * N_DIM);
        float4* dst = (float4*)sW;
#pragma unroll 4
        for (int i = tid; i < RPB * N_DIM / 4; i += NTHREADS) dst[i] = src[i];
    }
    if (tid < 8) { sGprog[tid] = 0; sCprog[tid] = 0; }
    const unsigned base = g_flags[b * 8];   // epoch (own slot, pre-release)
    __syncthreads();

    if (warp < 8) {
        // ============================ GEMM side ============================
        const int gr0 = b * RPB + 2 * warp;   // my two pre columns
        unsigned long long wXA[16], wXB[16];
        {
            const ulonglong2* A = (const ulonglong2*)(Wih + (size_t)gr0 * M_DIM);
            const ulonglong2* B = (const ulonglong2*)(Wih + (size_t)(gr0 + 1) * M_DIM);
#pragma unroll
            for (int i = 0; i < 8; i++) {
                ulonglong2 va = A[i * 32 + lane];
                ulonglong2 vb = B[i * 32 + lane];
                wXA[2 * i] = va.x;  wXA[2 * i + 1] = va.y;
                wXB[2 * i] = vb.x;  wXB[2 * i + 1] = vb.y;
            }
        }
        const float biasA = b_ih[gr0]     + b_hh[gr0];
        const float biasB = b_ih[gr0 + 1] + b_hh[gr0 + 1];

        for (int t0 = 0; t0 < T_STEPS; t0 += XG) {
            float* xb = sX + ((t0 >> 2) & 1) * (XG * M_DIM);

            barx(1);   // previous users of this buffer are done
            {          // stage X rows t0..t0+3 (16 KB, 256 threads)
                const float4* src = (const float4*)(X + (size_t)t0 * M_DIM);
                float4* dst = (float4*)xb;
#pragma unroll
                for (int k = 0; k < 4; k++) dst[tid + k * 256] = src[tid + k * 256];
            }
            barx(1);   // staged

            unsigned long long accA[XG], accB[XG];
#pragma unroll
            for (int r = 0; r < XG; r++) { accA[r] = 0ull; accB[r] = 0ull; }
#pragma unroll
            for (int i = 0; i < 8; i++) {
#pragma unroll
                for (int r = 0; r < XG; r++) {
                    ulonglong2 hv =
                        ((const ulonglong2*)(xb + r * M_DIM))[i * 32 + lane];
                    fma2(accA[r], wXA[2 * i],     hv.x);
                    fma2(accA[r], wXA[2 * i + 1], hv.y);
                    fma2(accB[r], wXB[2 * i],     hv.x);
                    fma2(accB[r], wXB[2 * i + 1], hv.y);
                }
            }
#pragma unroll
            for (int r = 0; r < XG; r++) {
                float sA = hsum2(accA[r]);
                float sB = hsum2(accB[r]);
#pragma unroll
                for (int o = 16; o; o >>= 1) {
                    sA += __shfl_xor_sync(0xffffffffu, sA, o);
                    sB += __shfl_xor_sync(0xffffffffu, sB, o);
                }
                if (lane == 0) {
                    const int t = t0 + r;
                    while (t - sCprog[warp] >= PRE_RING) { }  // backpressure
                    sPre[(t & (PRE_RING - 1)) * RPB + 2 * warp]     = sA + biasA;
                    sPre[(t & (PRE_RING - 1)) * RPB + 2 * warp + 1] = sB + biasB;
                    sts_rel_cta(&sGprog[warp], t + 1);        // release ring entry
                }
                __syncwarp();
            }
        }
    } else {
        // ============================ RNN side =============================
        const int w2   = warp - 8;
        const int row0 = b * RPB + 2 * w2;
        const int rtid = tid - 256;
        const ulonglong2* W0 = (const ulonglong2*)(sW + (size_t)(2 * w2) * N_DIM);
        const ulonglong2* W1 = (const ulonglong2*)(sW + (size_t)(2 * w2 + 1) * N_DIM);

        // Step 0: h_0 = 0  =>  Y[0] = tanh(pre[0]).
        if (lane == 0) {
            while (lds_acq_cta(&sGprog[w2]) < 1) { }
            float p0 = sPre[2 * w2];
            float p1 = sPre[2 * w2 + 1];
            float2 o;
            o.x = tanhf(p0);
            o.y = tanhf(p1);
            *(float2*)(Y + row0) = o;
            sCprog[w2] = 1;
        }
        barx(2);
        if (tid == 256) st_rel(&g_flags[b * 8], base + 1u);

        for (int t = 1; t < T_STEPS; t++) {
            const unsigned target = base + (unsigned)t;
            if (rtid < GBLOCKS) {
                while ((int)(ld_acq(&g_flags[rtid * 8]) - target) < 0) { }
            }
            barx(2);

            const ulonglong2* Yp = (const ulonglong2*)(Y + (size_t)(t - 1) * N_DIM);
            unsigned long long acc00 = 0ull, acc01 = 0ull,
                               acc10 = 0ull, acc11 = 0ull;
#pragma unroll
            for (int i = 0; i < 16; i++) {
                ulonglong2 hv = Yp[i * 32 + lane];
                ulonglong2 wa = W0[i * 32 + lane];
                ulonglong2 wb = W1[i * 32 + lane];
                fma2(acc00, wa.x, hv.x);
                fma2(acc01, wa.y, hv.y);
                fma2(acc10, wb.x, hv.x);
                fma2(acc11, wb.y, hv.y);
            }
            float r0 = hsum2(add2(acc00, acc01));
            float r1 = hsum2(add2(acc10, acc11));
#pragma unroll
            for (int o = 16; o; o >>= 1) {
                r0 += __shfl_xor_sync(0xffffffffu, r0, o);
                r1 += __shfl_xor_sync(0xffffffffu, r1, o);
            }

            if (lane == 0) {
                while (lds_acq_cta(&sGprog[w2]) < t + 1) { }  // ring fill (rarely waits)
                float p0 = sPre[(t & (PRE_RING - 1)) * RPB + 2 * w2];
                float p1 = sPre[(t & (PRE_RING - 1)) * RPB + 2 * w2 + 1];
                float2 o;
                o.x = tanhf(p0 + r0);
                o.y = tanhf(p1 + r1);
                *(float2*)(Y + (size_t)t * N_DIM + row0) = o;
                sCprog[w2] = t + 1;
            }
            barx(2);
            if (tid == 256) st_rel(&g_flags[b * 8], base + (unsigned)(t + 1));
        }
    }
}

// ---------------------------------------------------------------------------
extern "C" void kernel_launch(void* const* d_in, const int* in_sizes, int n_in,
                              void* d_out, int out_size)
{
    const float* X   = (const float*)d_in[0];   // [T, M]
    const float* Wih = (const float*)d_in[1];   // [N, M]
    const float* Whh = (const float*)d_in[2];   // [N, N]
    const float* bih = (const float*)d_in[3];   // [N]
    const float* bhh = (const float*)d_in[4];   // [N]
    float* Y = (float*)d_out;                   // [T, N]

    const size_t smem_bytes = (size_t)(32768 + 8192 + 1024) * sizeof(float);
    cudaFuncSetAttribute(rnn_fused_kernel,
                         cudaFuncAttributeMaxDynamicSharedMemorySize,
                         (int)smem_bytes);
    rnn_fused_kernel<<<GBLOCKS, NTHREADS, smem_bytes>>>(X, Wih, Whh, bih, bhh, Y);
}